// round 14
// baseline (speedup 1.0000x reference)
#include <cuda_runtime.h>

namespace {
constexpr int THREADS = 512;
constexpr int CH_STRIDE = 64 * 4 * 16 * 2 * 8;     // 65536 floats / batch
constexpr int NU = 2 * 4 * 2 * 8 * 16;             // 2048
constexpr int PRED_STRIDE = NU + 2 * 2 * 8 * 16;   // 2560
constexpr int A_LD = 66;
constexpr int NRHS = 16;
constexpr int CH_J = 32;       // j per chunk
constexpr int NCHUNK = 4;
constexpr int X_LD  = 68;      // padded jj-stride for X (floats)
constexpr int XOFF2 = 2180;    // padded d-plane stride for X (floats)
constexpr int ZOFF  = 2048;    // d-plane stride for Z (floats), jj stride 64

// dynamic smem (floats)
constexpr int OFF_A   = 0;                        // 64*66 f2 = 8448 f
constexpr int OFF_RHS = OFF_A + 64 * A_LD * 2;    // 2048 f
constexpr int OFF_XRE = OFF_RHS + 64 * NRHS * 2;  // 2*2180 = 4360 f
constexpr int OFF_XIM = OFF_XRE + 2 * XOFF2;      // 4360 f
constexpr int OFF_ZRE = OFF_XIM + 2 * XOFF2;      // 4096 f
constexpr int OFF_ZIM = OFF_ZRE + 4096;           // 4096 f
constexpr int OFF_U   = OFF_ZIM + 4096;           // [8][32] f2 = 512 f
constexpr int OFF_W   = OFF_U + 512;              // [32][4]   = 128 f
constexpr int SMEM_FLOATS = OFF_W + 128;
constexpr size_t SMEM_BYTES = (size_t)SMEM_FLOATS * 4;   // 112,192 B

typedef unsigned long long u64t;
}

__device__ __forceinline__ u64t pk2(float x, float y) {
    u64t r; asm("mov.b64 %0,{%1,%2};" : "=l"(r) : "f"(x), "f"(y)); return r;
}
__device__ __forceinline__ void f2fma(u64t& d, u64t a, u64t b) {
    asm("fma.rn.f32x2 %0,%1,%2,%0;" : "+l"(d) : "l"(a), "l"(b));
}
__device__ __forceinline__ float2 up2(u64t v) {
    float2 f; asm("mov.b64 {%0,%1},%2;" : "=f"(f.x), "=f"(f.y) : "l"(v)); return f;
}
__device__ __forceinline__ float2 cmul(float2 a, float2 b) {
    return make_float2(a.x * b.x - a.y * b.y, a.x * b.y + a.y * b.x);
}

__global__ void __launch_bounds__(THREADS, 2)
uw2v_kernel(const float* __restrict__ channel,
            const float* __restrict__ pred,
            float2* __restrict__ out)
{
    extern __shared__ float smf[];
    float2* sA   = (float2*)(smf + OFF_A);
    float2* srhs = (float2*)(smf + OFF_RHS);
    float*  sxre = smf + OFF_XRE;
    float*  sxim = smf + OFF_XIM;
    float*  szre = smf + OFF_ZRE;
    float*  szim = smf + OFF_ZIM;
    float2* su   = (float2*)(smf + OFF_U);
    float*  sw   = smf + OFF_W;

    __shared__ __align__(16) float2 prow[2][2][80];   // [buf][rowpair][skewed cols]
    __shared__ __align__(16) float2 prhs[2][2][16];
    __shared__ float2 wpart[16];
    __shared__ float  s_scale;

    const int b   = blockIdx.x;
    const int tid = threadIdx.x;
    const float* ch = channel + (size_t)b * CH_STRIDE;
    const float* pr = pred    + (size_t)b * PRED_STRIDE;

    const int warp = tid >> 5, lane = tid & 31;
    const int group = tid >> 8;          // 0/1: jj-split halves
    const int gtid  = tid & 255;
    const int ty = gtid >> 4, tx = gtid & 15;
    const int t0 = ty * 4, s0 = tx * 4;

    // phase-B mapping: warp spans only 4 t values -> 4-line LDG.128
    const int pb_t  = tid >> 3;
    const int pb_fl = (tid >> 2) & 1;
    const int pb_kh = (tid >> 1) & 1;
    const int pb_d  = tid & 1;

    u64t accre[2][4], accim[2][4];
    #pragma unroll
    for (int p = 0; p < 2; p++)
        #pragma unroll
        for (int s = 0; s < 4; s++) { accre[p][s] = 0ull; accim[p][s] = 0ull; }

    float2 rhsacc[2] = {{0,0},{0,0}};
    float trre = 0.f, trim = 0.f;

    for (int c = 0; c < NCHUNK; c++) {
        // ---- (A) load U chunk (256 f2) and W chunk (128 f) ----
        if (tid < 256) {
            int rd = tid >> 5, jj = tid & 31;
            int f = c * 4 + (jj >> 3), k = jj & 7;
            int base = (rd * 16 + f) * 16 + k;
            su[tid] = make_float2(pr[base], pr[base + 8]);
            if (tid < 128) {
                int jw = tid >> 2, de = tid & 3;
                int fw = c * 4 + (jw >> 3), kw = jw & 7;
                sw[tid] = pr[NU + (de * 16 + fw) * 8 + kw];
            }
        }
        __syncthreads();

        // ---- (B) X[d][jj][t] = sum_r conj(H)*U  (coalesced 4-line loads) ----
        #pragma unroll
        for (int fh = 0; fh < 2; fh++) {
            const int flg = fh * 2 + pb_fl;   // 0..3
            const float* chp = ch + pb_t * 1024 + (c * 4 + flg) * 16 + pb_kh * 4;
            float xr[4] = {0.f,0.f,0.f,0.f}, xi[4] = {0.f,0.f,0.f,0.f};
            #pragma unroll
            for (int r = 0; r < 4; r++) {
                float4 hre = *(const float4*)(chp + r * 256);
                float4 him = *(const float4*)(chp + r * 256 + 8);
                const float2* uptr = su + (r * 2 + pb_d) * 32 + flg * 8 + pb_kh * 4;
                float hr[4] = {hre.x, hre.y, hre.z, hre.w};
                float hi[4] = {him.x, him.y, him.z, him.w};
                #pragma unroll
                for (int kk = 0; kk < 4; kk++) {
                    float2 u = uptr[kk];
                    xr[kk] += hr[kk] * u.x + hi[kk] * u.y;
                    xi[kk] += hr[kk] * u.y - hi[kk] * u.x;
                }
            }
            #pragma unroll
            for (int kk = 0; kk < 4; kk++) {
                int jj = flg * 8 + pb_kh * 4 + kk;
                sxre[pb_d * XOFF2 + jj * X_LD + pb_t] = xr[kk];
                sxim[pb_d * XOFF2 + jj * X_LD + pb_t] = xi[kk];
            }
        }
        __syncthreads();

        // ---- (C) Z = W*conj(X) vectorized, rhs accumulate, trU accumulate ----
        #pragma unroll
        for (int h = 0; h < 4; h++) {
            int idx2 = tid + 512 * h;                 // d(1)|jj(5)|sp(5)
            int d = idx2 >> 10, jj = (idx2 >> 5) & 31, sp = (idx2 & 31) * 2;
            float w0 = sw[jj * 4 + d * 2];
            float w1 = sw[jj * 4 + d * 2 + 1];
            float2 x0r = *(const float2*)(sxre + jj * X_LD + sp);
            float2 x1r = *(const float2*)(sxre + XOFF2 + jj * X_LD + sp);
            float2 x0i = *(const float2*)(sxim + jj * X_LD + sp);
            float2 x1i = *(const float2*)(sxim + XOFF2 + jj * X_LD + sp);
            int zidx = d * ZOFF + jj * 64 + sp;
            *(float2*)(szre + zidx) = make_float2(w0 * x0r.x + w1 * x1r.x,
                                                  w0 * x0r.y + w1 * x1r.y);
            *(float2*)(szim + zidx) = make_float2(-(w0 * x0i.x + w1 * x1i.x),
                                                  -(w0 * x0i.y + w1 * x1i.y));
        }
        #pragma unroll
        for (int q = 0; q < 2; q++) {
            int item = tid + 512 * q;
            int t = item >> 4, cc = item & 15, e = cc >> 3, k = cc & 7;
            float sxr = 0.f, sxi = 0.f;
            #pragma unroll
            for (int fl = 0; fl < 4; fl++) {
                int jj = fl * 8 + k;
                float w0 = sw[jj * 4 + e];
                float w1 = sw[jj * 4 + 2 + e];
                sxr += sxre[jj * X_LD + t] * w0 + sxre[XOFF2 + jj * X_LD + t] * w1;
                sxi += sxim[jj * X_LD + t] * w0 + sxim[XOFF2 + jj * X_LD + t] * w1;
            }
            rhsacc[q].x += sxr; rhsacc[q].y += sxi;
        }
        if (tid < 128) {
            int r = tid >> 5, jj = tid & 31;
            float2 u0 = su[(r * 2) * 32 + jj];
            float2 u1 = su[(r * 2 + 1) * 32 + jj];
            const float* wj = sw + jj * 4;
            float cr = u0.x * u1.x + u0.y * u1.y;
            float ci = u0.y * u1.x - u0.x * u1.y;
            trre += wj[0] * (u0.x*u0.x + u0.y*u0.y) + wj[3] * (u1.x*u1.x + u1.y*u1.y)
                  + (wj[1] + wj[2]) * cr;
            trim += (wj[1] - wj[2]) * ci;
        }
        __syncthreads();

        // ---- (D) quad GEMM: group handles its 16 jj with 4x4 tile ----
        {
            const int jb = group * 16, je = jb + 16;
            #pragma unroll 1
            for (int jj = jb; jj < je; jj++) {
                #pragma unroll
                for (int d = 0; d < 2; d++) {
                    ulonglong2 ar = *(const ulonglong2*)(sxre + d * XOFF2 + jj * X_LD + t0);
                    ulonglong2 ai = *(const ulonglong2*)(sxim + d * XOFF2 + jj * X_LD + t0);
                    float4 zr = *(const float4*)(szre + d * ZOFF + jj * 64 + s0);
                    float4 zi = *(const float4*)(szim + d * ZOFF + jj * 64 + s0);
                    float zra[4] = {zr.x, zr.y, zr.z, zr.w};
                    float zia[4] = {zi.x, zi.y, zi.z, zi.w};
                    #pragma unroll
                    for (int s = 0; s < 4; s++) {
                        u64t Zr  = pk2(zra[s], zra[s]);
                        u64t Zi  = pk2(zia[s], zia[s]);
                        u64t Zni = pk2(-zia[s], -zia[s]);
                        f2fma(accre[0][s], ar.x, Zr);  f2fma(accre[0][s], ai.x, Zni);
                        f2fma(accim[0][s], ar.x, Zi);  f2fma(accim[0][s], ai.x, Zr);
                        f2fma(accre[1][s], ar.y, Zr);  f2fma(accre[1][s], ai.y, Zni);
                        f2fma(accim[1][s], ar.y, Zi);  f2fma(accim[1][s], ai.y, Zr);
                    }
                }
            }
        }
        __syncthreads();
    }

    // ---- trU warp reduce + group-1 partial store + rhs store ----
    #pragma unroll
    for (int o = 16; o; o >>= 1) {
        trre += __shfl_down_sync(0xffffffffu, trre, o);
        trim += __shfl_down_sync(0xffffffffu, trim, o);
    }
    if (lane == 0) wpart[warp] = make_float2(trre, trim);

    u64t* scratch = (u64t*)(smf + OFF_XRE);   // X/Z region reuse
    if (group == 1) {
        int base = gtid * 32;
        #pragma unroll
        for (int p = 0; p < 2; p++)
            #pragma unroll
            for (int s = 0; s < 4; s++) {
                scratch[base + p * 4 + s]     = accre[p][s];
                scratch[base + 8 + p * 4 + s] = accim[p][s];
            }
    }
    #pragma unroll
    for (int q = 0; q < 2; q++) srhs[tid + 512 * q] = rhsacc[q];
    __syncthreads();

    // ---- group 0 merges partials, writes A (+ trU*I) ----
    if (group == 0) {
        float sx = 0.f, sy = 0.f;
        #pragma unroll
        for (int i = 0; i < 16; i++) { sx += wpart[i].x; sy += wpart[i].y; }
        float2 trU = make_float2(0.1f * sx, 0.1f * sy);
        int base = gtid * 32;
        #pragma unroll
        for (int p = 0; p < 2; p++)
            #pragma unroll
            for (int s = 0; s < 4; s++) {
                float2 re2 = up2(accre[p][s]);
                float2 im2 = up2(accim[p][s]);
                float2 ore = up2(scratch[base + p * 4 + s]);
                float2 oim = up2(scratch[base + 8 + p * 4 + s]);
                re2.x += ore.x; re2.y += ore.y;
                im2.x += oim.x; im2.y += oim.y;
                int t = t0 + p * 2, col = s0 + s;
                float2 v0 = make_float2(re2.x, im2.x);
                float2 v1 = make_float2(re2.y, im2.y);
                if (t == col)     { v0.x += trU.x; v0.y += trU.y; }
                if (t + 1 == col) { v1.x += trU.x; v1.y += trU.y; }
                sA[t * A_LD + col]       = v0;
                sA[(t + 1) * A_LD + col] = v1;
            }
    }
    __syncthreads();

    // ---- register-resident block-2 Gauss-Jordan, 1 barrier per 2 columns ----
    const int r = tid >> 3, cg = tid & 7;
    float2 a[8]; float2 rr[2];
    #pragma unroll
    for (int j = 0; j < 8; j++) a[j] = sA[r * A_LD + cg * 8 + j];
    {
        float4 t4 = *(const float4*)(srhs + r * NRHS + cg * 2);
        rr[0] = make_float2(t4.x, t4.y);
        rr[1] = make_float2(t4.z, t4.w);
    }
    // publish rows 0,1 raw into buffer 0
    if (r < 2) {
        #pragma unroll
        for (int j = 0; j < 8; j++) prow[0][r][cg * 10 + j] = a[j];
        prhs[0][r][cg * 2]     = rr[0];
        prhs[0][r][cg * 2 + 1] = rr[1];
    }
    __syncthreads();

    #pragma unroll 1
    for (int blk = 0; blk < 32; blk++) {
        const int i0  = blk * 2;
        const int oct = i0 >> 3;
        const int jl  = i0 & 7;          // 0,2,4,6
        const int buf = blk & 1, nbuf = buf ^ 1;

        // 2x2 pivot block from raw published rows (16B-aligned pair load)
        float4 pA = *(const float4*)(prow[buf][0] + oct * 10 + jl);
        float4 pB = *(const float4*)(prow[buf][1] + oct * 10 + jl);
        float2 p00 = {pA.x, pA.y}, p01 = {pA.z, pA.w};
        float2 p10 = {pB.x, pB.y}, p11 = {pB.z, pB.w};
        // inverse of [[p00,p01],[p10,p11]]
        float2 m0 = cmul(p00, p11), m1 = cmul(p01, p10);
        float2 det = make_float2(m0.x - m1.x, m0.y - m1.y);
        float idn = 1.f / (det.x * det.x + det.y * det.y);
        float2 dinv = make_float2(det.x * idn, -det.y * idn);
        float2 q00 = cmul(p11, dinv);
        float2 q01 = make_float2(-p01.x, -p01.y); q01 = cmul(q01, dinv);
        float2 q10 = make_float2(-p10.x, -p10.y); q10 = cmul(q10, dinv);
        float2 q11 = cmul(p00, dinv);

        // this row's multiplier columns (in-warp broadcast from owner thread)
        float2 av0 = a[jl], av1 = a[jl + 1];
        const int srclane = ((r & 3) << 3) | oct;
        float2 f0, f1;
        f0.x = __shfl_sync(0xffffffffu, av0.x, srclane);
        f0.y = __shfl_sync(0xffffffffu, av0.y, srclane);
        f1.x = __shfl_sync(0xffffffffu, av1.x, srclane);
        f1.y = __shfl_sync(0xffffffffu, av1.y, srclane);

        if (r == i0 || r == i0 + 1) {
            // pivot rows: new row = Pinv[row] . raw rows
            float2 c0 = (r == i0) ? q00 : q10;
            float2 c1 = (r == i0) ? q01 : q11;
            #pragma unroll
            for (int j = 0; j < 8; j++) {
                float2 P0 = prow[buf][0][cg * 10 + j];
                float2 P1 = prow[buf][1][cg * 10 + j];
                float2 v = cmul(c0, P0);
                float2 w = cmul(c1, P1);
                a[j] = make_float2(v.x + w.x, v.y + w.y);
            }
            #pragma unroll
            for (int q = 0; q < 2; q++) {
                float2 P0 = prhs[buf][0][cg * 2 + q];
                float2 P1 = prhs[buf][1][cg * 2 + q];
                float2 v = cmul(c0, P0);
                float2 w = cmul(c1, P1);
                rr[q] = make_float2(v.x + w.x, v.y + w.y);
            }
        } else {
            // g = [f0 f1] . Pinv
            float2 g0a = cmul(f0, q00), g0b = cmul(f1, q10);
            float2 g1a = cmul(f0, q01), g1b = cmul(f1, q11);
            float2 g0 = make_float2(g0a.x + g0b.x, g0a.y + g0b.y);
            float2 g1 = make_float2(g1a.x + g1b.x, g1a.y + g1b.y);
            #pragma unroll
            for (int jp = 0; jp < 4; jp++) {
                float4 P0q = *(const float4*)(prow[buf][0] + cg * 10 + jp * 2);
                float4 P1q = *(const float4*)(prow[buf][1] + cg * 10 + jp * 2);
                a[jp*2].x   -= g0.x * P0q.x - g0.y * P0q.y + g1.x * P1q.x - g1.y * P1q.y;
                a[jp*2].y   -= g0.x * P0q.y + g0.y * P0q.x + g1.x * P1q.y + g1.y * P1q.x;
                a[jp*2+1].x -= g0.x * P0q.z - g0.y * P0q.w + g1.x * P1q.z - g1.y * P1q.w;
                a[jp*2+1].y -= g0.x * P0q.w + g0.y * P0q.z + g1.x * P1q.w + g1.y * P1q.z;
            }
            {
                float4 P0q = *(const float4*)(prhs[buf][0] + cg * 2);
                float4 P1q = *(const float4*)(prhs[buf][1] + cg * 2);
                rr[0].x -= g0.x * P0q.x - g0.y * P0q.y + g1.x * P1q.x - g1.y * P1q.y;
                rr[0].y -= g0.x * P0q.y + g0.y * P0q.x + g1.x * P1q.y + g1.y * P1q.x;
                rr[1].x -= g0.x * P0q.z - g0.y * P0q.w + g1.x * P1q.z - g1.y * P1q.w;
                rr[1].y -= g0.x * P0q.w + g0.y * P0q.z + g1.x * P1q.w + g1.y * P1q.z;
            }
            // next block's rows publish freshly-eliminated state
            if (r == i0 + 2 || r == i0 + 3) {
                int rp = r - (i0 + 2);
                #pragma unroll
                for (int j = 0; j < 8; j++) prow[nbuf][rp][cg * 10 + j] = a[j];
                prhs[nbuf][rp][cg * 2]     = rr[0];
                prhs[nbuf][rp][cg * 2 + 1] = rr[1];
            }
        }
        __syncthreads();
    }

    // ---- scatter solution: X[r] = this row's rhs ----
    *(float4*)(srhs + r * NRHS + cg * 2) =
        make_float4(rr[0].x, rr[0].y, rr[1].x, rr[1].y);
    __syncthreads();

    // ---- normalize + write out ----
    float ss = 0.f;
    #pragma unroll
    for (int q = 0; q < 2; q++) {
        float2 v = srhs[tid + 512 * q];
        ss += v.x * v.x + v.y * v.y;
    }
    #pragma unroll
    for (int o = 16; o; o >>= 1) ss += __shfl_down_sync(0xffffffffu, ss, o);
    if (lane == 0) wpart[warp].x = ss;
    __syncthreads();
    if (tid == 0) {
        float tot = 0.f;
        #pragma unroll
        for (int i = 0; i < 16; i++) tot += wpart[i].x;
        s_scale = rsqrtf(tot);   // P=1: total factor = 1/||V0||
    }
    __syncthreads();
    const float sc = s_scale;
    float2* op = out + (size_t)b * (64 * NRHS);
    #pragma unroll
    for (int q = 0; q < 2; q++) {
        float2 v = srhs[tid + 512 * q];
        op[tid + 512 * q] = make_float2(v.x * sc, v.y * sc);
    }
}

extern "C" void kernel_launch(void* const* d_in, const int* in_sizes, int n_in,
                              void* d_out, int out_size)
{
    const float* channel = (const float*)d_in[0];
    const float* pred    = (const float*)d_in[1];
    cudaFuncSetAttribute(uw2v_kernel, cudaFuncAttributeMaxDynamicSharedMemorySize,
                         (int)SMEM_BYTES);
    uw2v_kernel<<<256, THREADS, SMEM_BYTES, 0>>>(channel, pred, (float2*)d_out);
}

// round 15
// speedup vs baseline: 1.0723x; 1.0723x over previous
#include <cuda_runtime.h>

namespace {
constexpr int THREADS = 512;
constexpr int CH_STRIDE = 64 * 4 * 16 * 2 * 8;     // 65536 floats / batch
constexpr int NU = 2 * 4 * 2 * 8 * 16;             // 2048
constexpr int PRED_STRIDE = NU + 2 * 2 * 8 * 16;   // 2560
constexpr int A_LD = 66;
constexpr int NRHS = 16;
constexpr int CH_J = 32;       // j per chunk
constexpr int NCHUNK = 4;
constexpr int X_LD  = 68;      // padded jj-stride for X (floats)
constexpr int XOFF2 = 2180;    // padded d-plane stride for X (floats)
constexpr int ZOFF  = 2048;    // d-plane stride for Z (floats), jj stride 64

// dynamic smem (floats)
constexpr int OFF_A   = 0;                        // 64*66 f2 = 8448 f (aliased as U/W buffers during loop)
constexpr int OFF_RHS = OFF_A + 64 * A_LD * 2;    // 2048 f
constexpr int OFF_XRE = OFF_RHS + 64 * NRHS * 2;  // 2*2180 = 4360 f
constexpr int OFF_XIM = OFF_XRE + 2 * XOFF2;      // 4360 f
constexpr int OFF_ZRE = OFF_XIM + 2 * XOFF2;      // 4096 f
constexpr int OFF_ZIM = OFF_ZRE + 4096;           // 4096 f
constexpr int SMEM_FLOATS = OFF_ZIM + 4096;
constexpr size_t SMEM_BYTES = (size_t)SMEM_FLOATS * 4;

// aliased layout inside sA region during the main loop:
//   su[2][256] float2  at floats [0 .. 2048)
//   sw[2][128] float   at floats [2048 .. 2304)
constexpr int UBUF_F2 = 256;    // float2 per buffer
constexpr int WBUF_F  = 128;

typedef unsigned long long u64t;
}

__device__ __forceinline__ u64t pk2(float x, float y) {
    u64t r; asm("mov.b64 %0,{%1,%2};" : "=l"(r) : "f"(x), "f"(y)); return r;
}
__device__ __forceinline__ void f2fma(u64t& d, u64t a, u64t b) {
    asm("fma.rn.f32x2 %0,%1,%2,%0;" : "+l"(d) : "l"(a), "l"(b));
}
__device__ __forceinline__ float2 up2(u64t v) {
    float2 f; asm("mov.b64 {%0,%1},%2;" : "=f"(f.x), "=f"(f.y) : "l"(v)); return f;
}

__global__ void __launch_bounds__(THREADS, 2)
uw2v_kernel(const float* __restrict__ channel,
            const float* __restrict__ pred,
            float2* __restrict__ out)
{
    extern __shared__ float smf[];
    float2* sA   = (float2*)(smf + OFF_A);
    float2* srhs = (float2*)(smf + OFF_RHS);
    float*  sxre = smf + OFF_XRE;
    float*  sxim = smf + OFF_XIM;
    float*  szre = smf + OFF_ZRE;
    float*  szim = smf + OFF_ZIM;
    // double-buffered U/W aliased into the (loop-dead) sA region
    float2* suB  = (float2*)(smf + OFF_A);            // [2][256] float2
    float*  swB  = smf + OFF_A + 2 * UBUF_F2 * 2;     // [2][128] float

    __shared__ __align__(16) float2 prow[2][80];   // double-buffered, stride-10 skew
    __shared__ __align__(16) float2 prhs[2][16];
    __shared__ float2 wpart[16];
    __shared__ float  s_scale;

    const int b   = blockIdx.x;
    const int tid = threadIdx.x;
    const float* ch = channel + (size_t)b * CH_STRIDE;
    const float* pr = pred    + (size_t)b * PRED_STRIDE;

    const int warp = tid >> 5, lane = tid & 31;
    const int group = tid >> 8;          // 0/1: jj-split halves
    const int gtid  = tid & 255;
    const int ty = gtid >> 4, tx = gtid & 15;
    const int t0 = ty * 4, s0 = tx * 4;

    // phase-B mapping: warp spans only 4 t values -> 4-line LDG.128
    const int pb_t  = tid >> 3;
    const int pb_fl = (tid >> 2) & 1;
    const int pb_kh = (tid >> 1) & 1;
    const int pb_d  = tid & 1;

    u64t accre[2][4], accim[2][4];
    #pragma unroll
    for (int p = 0; p < 2; p++)
        #pragma unroll
        for (int s = 0; s < 4; s++) { accre[p][s] = 0ull; accim[p][s] = 0ull; }

    float2 rhsacc[2] = {{0,0},{0,0}};
    float trre = 0.f, trim = 0.f;

    // ---- preload chunk 0 U/W into buffer 0 ----
    if (tid < 256) {
        int rd = tid >> 5, jj = tid & 31;
        int f = (jj >> 3), k = jj & 7;
        int base = (rd * 16 + f) * 16 + k;
        suB[tid] = make_float2(pr[base], pr[base + 8]);
        if (tid < 128) {
            int jw = tid >> 2, de = tid & 3;
            int fw = (jw >> 3), kw = jw & 7;
            swB[tid] = pr[NU + (de * 16 + fw) * 8 + kw];
        }
    }
    __syncthreads();

    for (int c = 0; c < NCHUNK; c++) {
        const int cur = c & 1, nxt = cur ^ 1;
        float2* su = suB + cur * UBUF_F2;
        float*  sw = swB + cur * WBUF_F;

        // ---- (B) X[d][jj][t] = sum_r conj(H)*U  (coalesced 4-line loads) ----
        #pragma unroll
        for (int fh = 0; fh < 2; fh++) {
            const int flg = fh * 2 + pb_fl;   // 0..3
            const float* chp = ch + pb_t * 1024 + (c * 4 + flg) * 16 + pb_kh * 4;
            float xr[4] = {0.f,0.f,0.f,0.f}, xi[4] = {0.f,0.f,0.f,0.f};
            #pragma unroll
            for (int r = 0; r < 4; r++) {
                float4 hre = *(const float4*)(chp + r * 256);
                float4 him = *(const float4*)(chp + r * 256 + 8);
                const float2* uptr = su + (r * 2 + pb_d) * 32 + flg * 8 + pb_kh * 4;
                float hr[4] = {hre.x, hre.y, hre.z, hre.w};
                float hi[4] = {him.x, him.y, him.z, him.w};
                #pragma unroll
                for (int kk = 0; kk < 4; kk++) {
                    float2 u = uptr[kk];
                    xr[kk] += hr[kk] * u.x + hi[kk] * u.y;
                    xi[kk] += hr[kk] * u.y - hi[kk] * u.x;
                }
            }
            #pragma unroll
            for (int kk = 0; kk < 4; kk++) {
                int jj = flg * 8 + pb_kh * 4 + kk;
                sxre[pb_d * XOFF2 + jj * X_LD + pb_t] = xr[kk];
                sxim[pb_d * XOFF2 + jj * X_LD + pb_t] = xi[kk];
            }
        }
        // ---- prefetch next chunk's U/W into the other buffer ----
        if (c + 1 < NCHUNK && tid < 256) {
            int rd = tid >> 5, jj = tid & 31;
            int f = (c + 1) * 4 + (jj >> 3), k = jj & 7;
            int base = (rd * 16 + f) * 16 + k;
            suB[nxt * UBUF_F2 + tid] = make_float2(pr[base], pr[base + 8]);
            if (tid < 128) {
                int jw = tid >> 2, de = tid & 3;
                int fw = (c + 1) * 4 + (jw >> 3), kw = jw & 7;
                swB[nxt * WBUF_F + tid] = pr[NU + (de * 16 + fw) * 8 + kw];
            }
        }
        __syncthreads();

        // ---- (C) Z = W*conj(X) vectorized, rhs accumulate, trU accumulate ----
        #pragma unroll
        for (int h = 0; h < 4; h++) {
            int idx2 = tid + 512 * h;                 // d(1)|jj(5)|sp(5)
            int d = idx2 >> 10, jj = (idx2 >> 5) & 31, sp = (idx2 & 31) * 2;
            float w0 = sw[jj * 4 + d * 2];
            float w1 = sw[jj * 4 + d * 2 + 1];
            float2 x0r = *(const float2*)(sxre + jj * X_LD + sp);
            float2 x1r = *(const float2*)(sxre + XOFF2 + jj * X_LD + sp);
            float2 x0i = *(const float2*)(sxim + jj * X_LD + sp);
            float2 x1i = *(const float2*)(sxim + XOFF2 + jj * X_LD + sp);
            int zidx = d * ZOFF + jj * 64 + sp;
            *(float2*)(szre + zidx) = make_float2(w0 * x0r.x + w1 * x1r.x,
                                                  w0 * x0r.y + w1 * x1r.y);
            *(float2*)(szim + zidx) = make_float2(-(w0 * x0i.x + w1 * x1i.x),
                                                  -(w0 * x0i.y + w1 * x1i.y));
        }
        #pragma unroll
        for (int q = 0; q < 2; q++) {
            int item = tid + 512 * q;
            int t = item >> 4, cc = item & 15, e = cc >> 3, k = cc & 7;
            float sxr = 0.f, sxi = 0.f;
            #pragma unroll
            for (int fl = 0; fl < 4; fl++) {
                int jj = fl * 8 + k;
                float w0 = sw[jj * 4 + e];
                float w1 = sw[jj * 4 + 2 + e];
                sxr += sxre[jj * X_LD + t] * w0 + sxre[XOFF2 + jj * X_LD + t] * w1;
                sxi += sxim[jj * X_LD + t] * w0 + sxim[XOFF2 + jj * X_LD + t] * w1;
            }
            rhsacc[q].x += sxr; rhsacc[q].y += sxi;
        }
        if (tid < 128) {
            int r = tid >> 5, jj = tid & 31;
            float2 u0 = su[(r * 2) * 32 + jj];
            float2 u1 = su[(r * 2 + 1) * 32 + jj];
            const float* wj = sw + jj * 4;
            float cr = u0.x * u1.x + u0.y * u1.y;
            float ci = u0.y * u1.x - u0.x * u1.y;
            trre += wj[0] * (u0.x*u0.x + u0.y*u0.y) + wj[3] * (u1.x*u1.x + u1.y*u1.y)
                  + (wj[1] + wj[2]) * cr;
            trim += (wj[1] - wj[2]) * ci;
        }
        __syncthreads();

        // ---- (D) quad GEMM: group handles its 16 jj with 4x4 tile ----
        {
            const int jb = group * 16, je = jb + 16;
            #pragma unroll 1
            for (int jj = jb; jj < je; jj++) {
                #pragma unroll
                for (int d = 0; d < 2; d++) {
                    ulonglong2 ar = *(const ulonglong2*)(sxre + d * XOFF2 + jj * X_LD + t0);
                    ulonglong2 ai = *(const ulonglong2*)(sxim + d * XOFF2 + jj * X_LD + t0);
                    float4 zr = *(const float4*)(szre + d * ZOFF + jj * 64 + s0);
                    float4 zi = *(const float4*)(szim + d * ZOFF + jj * 64 + s0);
                    float zra[4] = {zr.x, zr.y, zr.z, zr.w};
                    float zia[4] = {zi.x, zi.y, zi.z, zi.w};
                    #pragma unroll
                    for (int s = 0; s < 4; s++) {
                        u64t Zr  = pk2(zra[s], zra[s]);
                        u64t Zi  = pk2(zia[s], zia[s]);
                        u64t Zni = pk2(-zia[s], -zia[s]);
                        f2fma(accre[0][s], ar.x, Zr);  f2fma(accre[0][s], ai.x, Zni);
                        f2fma(accim[0][s], ar.x, Zi);  f2fma(accim[0][s], ai.x, Zr);
                        f2fma(accre[1][s], ar.y, Zr);  f2fma(accre[1][s], ai.y, Zni);
                        f2fma(accim[1][s], ar.y, Zi);  f2fma(accim[1][s], ai.y, Zr);
                    }
                }
            }
        }
        __syncthreads();
    }

    // ---- trU warp reduce + group-1 partial store + rhs store ----
    #pragma unroll
    for (int o = 16; o; o >>= 1) {
        trre += __shfl_down_sync(0xffffffffu, trre, o);
        trim += __shfl_down_sync(0xffffffffu, trim, o);
    }
    if (lane == 0) wpart[warp] = make_float2(trre, trim);

    u64t* scratch = (u64t*)(smf + OFF_XRE);   // X/Z region reuse
    if (group == 1) {
        int base = gtid * 32;
        #pragma unroll
        for (int p = 0; p < 2; p++)
            #pragma unroll
            for (int s = 0; s < 4; s++) {
                scratch[base + p * 4 + s]     = accre[p][s];
                scratch[base + 8 + p * 4 + s] = accim[p][s];
            }
    }
    #pragma unroll
    for (int q = 0; q < 2; q++) srhs[tid + 512 * q] = rhsacc[q];
    __syncthreads();

    // ---- group 0 merges partials, writes A (+ trU*I) ----
    if (group == 0) {
        float sx = 0.f, sy = 0.f;
        #pragma unroll
        for (int i = 0; i < 16; i++) { sx += wpart[i].x; sy += wpart[i].y; }
        float2 trU = make_float2(0.1f * sx, 0.1f * sy);
        int base = gtid * 32;
        #pragma unroll
        for (int p = 0; p < 2; p++)
            #pragma unroll
            for (int s = 0; s < 4; s++) {
                float2 re2 = up2(accre[p][s]);
                float2 im2 = up2(accim[p][s]);
                float2 ore = up2(scratch[base + p * 4 + s]);
                float2 oim = up2(scratch[base + 8 + p * 4 + s]);
                re2.x += ore.x; re2.y += ore.y;
                im2.x += oim.x; im2.y += oim.y;
                int t = t0 + p * 2, col = s0 + s;
                float2 v0 = make_float2(re2.x, im2.x);
                float2 v1 = make_float2(re2.y, im2.y);
                if (t == col)     { v0.x += trU.x; v0.y += trU.y; }
                if (t + 1 == col) { v1.x += trU.x; v1.y += trU.y; }
                sA[t * A_LD + col]       = v0;
                sA[(t + 1) * A_LD + col] = v1;
            }
    }
    __syncthreads();

    // ---- register-resident Gauss-Jordan, NO pivot search, 1 barrier/iter ----
    const int r = tid >> 3, cg = tid & 7;
    float2 a[8]; float2 rr[2];
    #pragma unroll
    for (int j = 0; j < 8; j++) a[j] = sA[r * A_LD + cg * 8 + j];
    {
        float4 t4 = *(const float4*)(srhs + r * NRHS + cg * 2);
        rr[0] = make_float2(t4.x, t4.y);
        rr[1] = make_float2(t4.z, t4.w);
    }
    // publish row 0 (raw) into buffer 0
    if (r == 0) {
        #pragma unroll
        for (int j = 0; j < 8; j++) prow[0][cg * 10 + j] = a[j];
        prhs[0][cg * 2]     = rr[0];
        prhs[0][cg * 2 + 1] = rr[1];
    }
    __syncthreads();

    for (int oct = 0; oct < 8; oct++) {
        #pragma unroll
        for (int jl = 0; jl < 8; jl++) {
            const int i = oct * 8 + jl;
            const int buf = i & 1, nbuf = buf ^ 1;
            // pivot element of the published (raw) row i
            float2 dv = prow[buf][oct * 10 + jl];
            float inv = 1.f / (dv.x * dv.x + dv.y * dv.y);
            float2 pinv = make_float2(dv.x * inv, -dv.y * inv);
            // in-warp broadcast of this row's column-i value
            float2 av = a[jl];
            const int srclane = ((r & 3) << 3) | oct;
            float fvx = __shfl_sync(0xffffffffu, av.x, srclane);
            float fvy = __shfl_sync(0xffffffffu, av.y, srclane);
            if (r == i) {
                // pivot row: normalize in registers
                #pragma unroll
                for (int j = 0; j < 8; j++) {
                    float2 v = a[j];
                    a[j] = make_float2(v.x * pinv.x - v.y * pinv.y,
                                       v.x * pinv.y + v.y * pinv.x);
                }
                float2 v0 = rr[0], v1 = rr[1];
                rr[0] = make_float2(v0.x * pinv.x - v0.y * pinv.y,
                                    v0.x * pinv.y + v0.y * pinv.x);
                rr[1] = make_float2(v1.x * pinv.x - v1.y * pinv.y,
                                    v1.x * pinv.y + v1.y * pinv.x);
            } else {
                float f_x = fvx * pinv.x - fvy * pinv.y;
                float f_y = fvx * pinv.y + fvy * pinv.x;
                #pragma unroll
                for (int jp = 0; jp < 4; jp++) {
                    float4 pq = *(const float4*)(prow[buf] + cg * 10 + jp * 2);
                    a[jp*2].x   -= f_x * pq.x - f_y * pq.y;
                    a[jp*2].y   -= f_x * pq.y + f_y * pq.x;
                    a[jp*2+1].x -= f_x * pq.z - f_y * pq.w;
                    a[jp*2+1].y -= f_x * pq.w + f_y * pq.z;
                }
                float4 pb = *(const float4*)(prhs[buf] + cg * 2);
                rr[0].x -= f_x * pb.x - f_y * pb.y;
                rr[0].y -= f_x * pb.y + f_y * pb.x;
                rr[1].x -= f_x * pb.z - f_y * pb.w;
                rr[1].y -= f_x * pb.w + f_y * pb.z;
                // freshly-eliminated next pivot row publishes into the other buffer
                if (r == i + 1) {
                    #pragma unroll
                    for (int j = 0; j < 8; j++) prow[nbuf][cg * 10 + j] = a[j];
                    prhs[nbuf][cg * 2]     = rr[0];
                    prhs[nbuf][cg * 2 + 1] = rr[1];
                }
            }
            __syncthreads();
        }
    }

    // ---- scatter solution: X[r] = this row's rhs ----
    *(float4*)(srhs + r * NRHS + cg * 2) =
        make_float4(rr[0].x, rr[0].y, rr[1].x, rr[1].y);
    __syncthreads();

    // ---- normalize + write out ----
    float ss = 0.f;
    #pragma unroll
    for (int q = 0; q < 2; q++) {
        float2 v = srhs[tid + 512 * q];
        ss += v.x * v.x + v.y * v.y;
    }
    #pragma unroll
    for (int o = 16; o; o >>= 1) ss += __shfl_down_sync(0xffffffffu, ss, o);
    if (lane == 0) wpart[warp].x = ss;
    __syncthreads();
    if (tid == 0) {
        float tot = 0.f;
        #pragma unroll
        for (int i = 0; i < 16; i++) tot += wpart[i].x;
        s_scale = rsqrtf(tot);   // P=1: total factor = 1/||V0||
    }
    __syncthreads();
    const float sc = s_scale;
    float2* op = out + (size_t)b * (64 * NRHS);
    #pragma unroll
    for (int q = 0; q < 2; q++) {
        float2 v = srhs[tid + 512 * q];
        op[tid + 512 * q] = make_float2(v.x * sc, v.y * sc);
    }
}

extern "C" void kernel_launch(void* const* d_in, const int* in_sizes, int n_in,
                              void* d_out, int out_size)
{
    const float* channel = (const float*)d_in[0];
    const float* pred    = (const float*)d_in[1];
    cudaFuncSetAttribute(uw2v_kernel, cudaFuncAttributeMaxDynamicSharedMemorySize,
                         (int)SMEM_BYTES);
    uw2v_kernel<<<256, THREADS, SMEM_BYTES, 0>>>(channel, pred, (float2*)d_out);
}